// round 13
// baseline (speedup 1.0000x reference)
#include <cuda_runtime.h>
#include <cstdint>
#include <cstddef>

// ---------------- problem constants ----------------
#define BATCH 32
#define C 64
#define C4 16

// Compile-time filter constants: fold into FFMA immediates.
static __device__ constexpr float HH0[8] = {
    0.0322231f, -0.01260397f, -0.09921954f, 0.2978578f,
    0.80373875f, 0.49761867f, -0.02963553f, -0.07576571f};
static __device__ constexpr float HH1[8] = {
    0.07576571f, -0.02963553f, -0.49761867f, 0.80373875f,
   -0.2978578f, -0.09921954f, 0.01260397f, 0.0322231f};
// g = reverse(h)
static __device__ constexpr float GG0[8] = {
   -0.07576571f, -0.02963553f, 0.49761867f, 0.80373875f,
    0.2978578f, -0.09921954f, -0.01260397f, 0.0322231f};
static __device__ constexpr float GG1[8] = {
    0.0322231f, 0.01260397f, -0.09921954f, -0.2978578f,
    0.80373875f, -0.49761867f, -0.02963553f, 0.07576571f};

// ---------------- scratch (static __device__, no allocs) ----------------
#define SUBSZ  (BATCH*32*32*64)

// padded y1: per b plane 72x72 pixels, interior at (3..66, 3..66)
#define Y1W    72
#define Y1PIX  (Y1W*Y1W)

// padded mix: per (s,b) plane 36x36, interior (1..32)
#define MIXW   36
#define MIXPIX (MIXW*MIXW)
#define MIXSUBSTRIDE_F2 (32*MIXPIX*32)   // float2 stride between subbands

// padded res: per b plane 68x68, interior (1..64)
#define RESW   68
#define RESPIX (RESW*RESW)

static __device__ float g_y1 [BATCH*(size_t)Y1PIX*64];     // padded, pads stay zero
static __device__ float g_sub[4*SUBSZ];
static __device__ float g_mix[4*BATCH*(size_t)MIXPIX*64];  // padded, pads stay zero
static __device__ float g_res[BATCH*(size_t)RESPIX*64];    // padded, pads stay zero

__device__ __forceinline__ float4 f4z() { return make_float4(0.f,0.f,0.f,0.f); }
__device__ __forceinline__ float4 f4fma(float4 a, float s, float4 v) {
    a.x = fmaf(s, v.x, a.x); a.y = fmaf(s, v.y, a.y);
    a.z = fmaf(s, v.z, a.z); a.w = fmaf(s, v.w, a.w);
    return a;
}
__device__ __forceinline__ float2 f2z() { return make_float2(0.f,0.f); }
__device__ __forceinline__ float2 f2fma(float2 a, float s, float2 v) {
    a.x = fmaf(s, v.x, a.x); a.y = fmaf(s, v.y, a.y);
    return a;
}
__device__ __forceinline__ unsigned long long dup2(float a) {
    unsigned long long r;
    asm("mov.b64 %0, {%1, %1};" : "=l"(r) : "f"(a));
    return r;
}
__device__ __forceinline__ unsigned long long pk2(float x, float y) {
    unsigned long long r;
    asm("mov.b64 %0, {%1, %2};" : "=l"(r) : "f"(x), "f"(y));
    return r;
}
__device__ __forceinline__ void unpk2(unsigned long long v, float& lo, float& hi) {
    asm("mov.b64 {%0, %1}, %2;" : "=f"(lo), "=f"(hi) : "l"(v));
}

// =====================================================================
// Stage 1: level-1 LL DWT, float2 lanes + x-polyphase pairing.
// x(B,128,128,64) -> padded g_y1.
// block 128 = 32 lanes (ch-pairs) x 4 xo-pairs;
// grid (8 xtiles, 8 ychunks(8), B)
// =====================================================================
__global__ __launch_bounds__(128) void k_dwt1(const float* __restrict__ x) {
    const int lane = threadIdx.x & 31;                        // ch pair
    const int xo   = ((blockIdx.x << 2) + (threadIdx.x >> 5)) << 1;  // even 0..62
    const int y0   = blockIdx.y << 3;
    const int b    = blockIdx.z;
    const float2* __restrict__ xin =
        reinterpret_cast<const float2*>(x) + (size_t)b * (128*128*32) + lane;

    // 10 shared columns for the pair; edge-clamped offsets + zeroed weights
    const int cb = 2*xo - 3;
    int   xoff[10];
    float we[10], wo[10];
    #pragma unroll
    for (int cc = 0; cc < 10; ++cc) {
        const int xi = cb + cc;
        const bool v = (xi >= 0 && xi < 128);
        xoff[cc] = (v ? xi : 0) * 32;
        we[cc] = (v && cc < 8)  ? HH0[cc]     : 0.f;
        wo[cc] = (v && cc >= 2) ? HH0[cc - 2] : 0.f;
    }

    float2 HE[8], HO[8];

    #define DROW(REL) do {                                                   \
        const int r_ = 2*y0 + (REL);                                         \
        float2 he = f2z(), ho = f2z();                                       \
        if (r_ >= 0 && r_ < 128) {                                           \
            const size_t rb = (size_t)r_ * (128*32);                         \
            _Pragma("unroll")                                                \
            for (int cc = 0; cc < 10; ++cc) {                                \
                const float2 v = xin[rb + xoff[cc]];                         \
                he = f2fma(he, we[cc], v);                                   \
                ho = f2fma(ho, wo[cc], v);                                   \
            }                                                                \
        }                                                                    \
        HE[((REL) + 16) & 7] = he; HO[((REL) + 16) & 7] = ho;                \
    } while (0)

    DROW(-3); DROW(-2); DROW(-1); DROW(0); DROW(1); DROW(2);

    float2* __restrict__ yout = reinterpret_cast<float2*>(g_y1)
        + ((size_t)b*Y1PIX + (size_t)(y0 + 3)*Y1W + (xo + 3))*32 + lane;

    #pragma unroll
    for (int yy = 0; yy < 8; ++yy) {
        DROW(2*yy + 3);
        DROW(2*yy + 4);
        float2 ae = f2z(), ao = f2z();
        #pragma unroll
        for (int k = 0; k < 8; ++k) {
            const int r = (2*yy - 3 + k + 16) & 7;
            ae = f2fma(ae, HH0[k], HE[r]);
            ao = f2fma(ao, HH0[k], HO[r]);
        }
        yout[(size_t)yy * (Y1W*32)]      = ae;
        yout[(size_t)yy * (Y1W*32) + 32] = ao;
    }
    #undef DROW
}

// =====================================================================
// Stage 2: level-2 DWT, float2 lanes + x-polyphase pairing, padded
// input so ALL weights are compile-time immediates (no weight regs).
// g_y1 -> g_sub. block 128 = 32 lanes x 4 xo-pairs;
// grid (4 xtiles, 8 ychunks(4), B)
// =====================================================================
__global__ __launch_bounds__(128) void k_dwt2() {
    const int lane = threadIdx.x & 31;
    const int xo   = ((blockIdx.x << 2) + (threadIdx.x >> 5)) << 1;  // even 0..30
    const int y0   = blockIdx.y << 2;                                // 4 per chunk
    const int b    = blockIdx.z;
    const float2* __restrict__ in =
        reinterpret_cast<const float2*>(g_y1) + (size_t)b * (Y1PIX*32) + lane;

    float2 H0E[8], H0O[8], H1E[8], H1O[8];

    // padded row = 2*y0 + REL + 3; padded col base = 2*xo (10 cols)
    #define D2ROW(REL) do {                                                  \
        const size_t rb = (size_t)(2*y0 + (REL) + 3) * (Y1W*32)              \
                        + (size_t)(2*xo)*32;                                 \
        float2 v[10];                                                        \
        _Pragma("unroll")                                                    \
        for (int cc = 0; cc < 10; ++cc) v[cc] = in[rb + (size_t)cc*32];      \
        float2 a0e = f2z(), a0o = f2z(), a1e = f2z(), a1o = f2z();           \
        _Pragma("unroll")                                                    \
        for (int k = 0; k < 8; ++k) {                                        \
            a0e = f2fma(a0e, HH0[k], v[k]);                                  \
            a1e = f2fma(a1e, HH1[k], v[k]);                                  \
            a0o = f2fma(a0o, HH0[k], v[k + 2]);                              \
            a1o = f2fma(a1o, HH1[k], v[k + 2]);                              \
        }                                                                    \
        H0E[((REL) + 16) & 7] = a0e; H1E[((REL) + 16) & 7] = a1e;            \
        H0O[((REL) + 16) & 7] = a0o; H1O[((REL) + 16) & 7] = a1o;            \
    } while (0)

    D2ROW(-3); D2ROW(-2); D2ROW(-1); D2ROW(0); D2ROW(1); D2ROW(2);

    float2* __restrict__ sub = reinterpret_cast<float2*>(g_sub);

    #pragma unroll
    for (int yy = 0; yy < 4; ++yy) {
        D2ROW(2*yy + 3);
        D2ROW(2*yy + 4);
        float2 llE = f2z(), lhE = f2z(), hlE = f2z(), hhE = f2z();
        float2 llO = f2z(), lhO = f2z(), hlO = f2z(), hhO = f2z();
        #pragma unroll
        for (int k = 0; k < 8; ++k) {
            const int r = (2*yy - 3 + k + 16) & 7;
            llE = f2fma(llE, HH0[k], H0E[r]);
            lhE = f2fma(lhE, HH0[k], H1E[r]);
            hlE = f2fma(hlE, HH1[k], H0E[r]);
            hhE = f2fma(hhE, HH1[k], H1E[r]);
            llO = f2fma(llO, HH0[k], H0O[r]);
            lhO = f2fma(lhO, HH0[k], H1O[r]);
            hlO = f2fma(hlO, HH1[k], H0O[r]);
            hhO = f2fma(hhO, HH1[k], H1O[r]);
        }
        const size_t o = (((size_t)(b*32 + y0 + yy))*32 + xo)*32 + lane;
        sub[o + 0*(size_t)(SUBSZ/2)]      = llE;
        sub[o + 1*(size_t)(SUBSZ/2)]      = lhE;
        sub[o + 2*(size_t)(SUBSZ/2)]      = hlE;
        sub[o + 3*(size_t)(SUBSZ/2)]      = hhE;
        sub[o + 0*(size_t)(SUBSZ/2) + 32] = llO;
        sub[o + 1*(size_t)(SUBSZ/2) + 32] = lhO;
        sub[o + 2*(size_t)(SUBSZ/2) + 32] = hlO;
        sub[o + 3*(size_t)(SUBSZ/2) + 32] = hhO;
    }
    #undef D2ROW
}

// =====================================================================
// Fused channel mixing (round-12 form, measured good).
// =====================================================================
__global__ __launch_bounds__(256) void k_mixw(const float* __restrict__ w1,
                                              const float* __restrict__ w2,
                                              const float* __restrict__ w3,
                                              const float* __restrict__ w4) {
    const int s  = blockIdx.z;
    const int h  = blockIdx.y;
    const int w0 = blockIdx.x * 4;

    const float* __restrict__ Wg =
        (s == 0) ? w1 : (s == 1) ? w2 : (s == 2) ? w3 : w4;
    const float* __restrict__ A = g_sub + (size_t)s * SUBSZ;

    __shared__ float Ws[16*4*64];   // [i16][w4][o64]  16KB
    __shared__ float As[4*16*32];   // [w4][i16][b32]   8KB

    const int t    = threadIdx.x;
    const int wl   = t >> 5;        // 0..7
    const int wloc = wl & 3;        // local w
    const int o0   = (wl >> 2) * 32;// o half
    const int lane = t & 31;
    const int og   = lane & 7;      // o = o0 + og*4 .. +3
    const int bg   = lane >> 3;     // b = bg*8 .. +7

    unsigned long long acc[4][4];
    #pragma unroll
    for (int j = 0; j < 4; ++j)
        #pragma unroll
        for (int p = 0; p < 4; ++p) acc[j][p] = 0ull;

    const int a_b = t & 31;
    const int a_w = (t >> 5) & 3;
    const int a_i = (t >> 7) * 8;

    #pragma unroll 1
    for (int ic = 0; ic < 4; ++ic) {
        const int ib = ic * 16;
        if (ic) __syncthreads();

        #pragma unroll
        for (int r = 0; r < 4; ++r) {
            const int id = t + 256*r;
            const int o  = id & 63;
            const int i  = id >> 6;
            const float4 v = *reinterpret_cast<const float4*>(
                &Wg[((size_t)(ib + i)*64 + o)*1024 + h*32 + w0]);
            const int base = i*4*64 + o;
            Ws[base + 0*64] = v.x;
            Ws[base + 1*64] = v.y;
            Ws[base + 2*64] = v.z;
            Ws[base + 3*64] = v.w;
        }

        #pragma unroll
        for (int i4 = 0; i4 < 2; ++i4) {
            const float4 v = *reinterpret_cast<const float4*>(
                &A[((size_t)(a_b*32 + h)*32 + w0 + a_w)*64 + ib + a_i + i4*4]);
            const int base = (a_w*16 + a_i + i4*4)*32 + a_b;
            As[base + 0*32] = v.x;
            As[base + 1*32] = v.y;
            As[base + 2*32] = v.z;
            As[base + 3*32] = v.w;
        }
        __syncthreads();

        #pragma unroll
        for (int i = 0; i < 16; ++i) {
            const float4 a0 = *reinterpret_cast<const float4*>(
                &As[(wloc*16 + i)*32 + bg*8]);
            const float4 a1 = *reinterpret_cast<const float4*>(
                &As[(wloc*16 + i)*32 + bg*8 + 4]);
            const float4 wv = *reinterpret_cast<const float4*>(
                &Ws[(i*4 + wloc)*64 + o0 + og*4]);

            unsigned long long ap[4];
            ap[0] = pk2(a0.x, a0.y);
            ap[1] = pk2(a0.z, a0.w);
            ap[2] = pk2(a1.x, a1.y);
            ap[3] = pk2(a1.z, a1.w);
            unsigned long long wd[4];
            wd[0] = dup2(wv.x);
            wd[1] = dup2(wv.y);
            wd[2] = dup2(wv.z);
            wd[3] = dup2(wv.w);

            #pragma unroll
            for (int j = 0; j < 4; ++j)
                #pragma unroll
                for (int p = 0; p < 4; ++p)
                    asm("fma.rn.f32x2 %0, %1, %2, %0;"
                        : "+l"(acc[j][p]) : "l"(ap[p]), "l"(wd[j]));
        }
    }

    float af[4][8];
    #pragma unroll
    for (int j = 0; j < 4; ++j)
        #pragma unroll
        for (int p = 0; p < 4; ++p)
            unpk2(acc[j][p], af[j][2*p], af[j][2*p + 1]);

    #pragma unroll
    for (int jb = 0; jb < 8; ++jb) {
        const int b = bg*8 + jb;
        float4 v = make_float4(af[0][jb], af[1][jb], af[2][jb], af[3][jb]);
        const size_t px = ((size_t)(s*32 + b)*MIXW + (h + 1))*MIXW + (w0 + wloc + 1);
        *reinterpret_cast<float4*>(&g_mix[px*64 + o0 + og*4]) = v;
    }
}

// =====================================================================
// Recon level 2 -> 1 (padded, polyphase-paired xo, float2 lanes,
// immediate coefficients). (round-10, measured good)
// =====================================================================
__global__ __launch_bounds__(128) void k_rec1() {
    const int lane = threadIdx.x & 31;                       // float2 ch index
    const int xo   = ((blockIdx.x << 2) + (threadIdx.x >> 5)) << 1;  // even
    const int y0   = blockIdx.y << 3;
    const int b    = blockIdx.z;

    const int vb = xo >> 1;

    const float2* __restrict__ m0 = reinterpret_cast<const float2*>(g_mix)
        + (size_t)b * (MIXPIX*32) + lane;
    const float2* __restrict__ m1 = m0 + 1*(size_t)MIXSUBSTRIDE_F2;
    const float2* __restrict__ m2 = m0 + 2*(size_t)MIXSUBSTRIDE_F2;
    const float2* __restrict__ m3 = m0 + 3*(size_t)MIXSUBSTRIDE_F2;

    float2 PE[4], QE[4], PO[4], QO[4];
    const int ub = ((y0 - 2) >> 1) + 1;

    #define MKROW1(REL) do {                                                 \
        const size_t rb = ((size_t)(ub + (REL))*MIXW + vb)*32;               \
        float2 pe = f2z(), qe = f2z(), po = f2z(), qo = f2z();               \
        _Pragma("unroll")                                                    \
        for (int j = 0; j < 4; ++j) {                                        \
            const size_t ix = rb + (size_t)j*32;                             \
            const float2 aft = m0[ix], alh = m1[ix];                         \
            const float2 ahl = m2[ix], ahh = m3[ix];                         \
            pe = f2fma(pe, GG0[1+2*j], aft); pe = f2fma(pe, GG1[1+2*j], alh);\
            qe = f2fma(qe, GG0[1+2*j], ahl); qe = f2fma(qe, GG1[1+2*j], ahh);\
            po = f2fma(po, GG0[2*j],   aft); po = f2fma(po, GG1[2*j],   alh);\
            qo = f2fma(qo, GG0[2*j],   ahl); qo = f2fma(qo, GG1[2*j],   ahh);\
        }                                                                    \
        PE[(REL) & 3] = pe; QE[(REL) & 3] = qe;                              \
        PO[(REL) & 3] = po; QO[(REL) & 3] = qo;                              \
    } while (0)

    MKROW1(0); MKROW1(1); MKROW1(2); MKROW1(3);

    float2* __restrict__ out = reinterpret_cast<float2*>(g_res)
        + (((size_t)b*RESW + (y0 + 1))*RESW + (xo + 1))*32 + lane;

    #pragma unroll
    for (int yy = 0; yy < 8; ++yy) {
        if (yy >= 2 && (yy & 1) == 0) {
            MKROW1(yy/2 + 3);
        }
        float2 ae = f2z(), ao = f2z();
        const int ky0 = (yy & 1) ^ 1;
        #pragma unroll
        for (int j = 0; j < 4; ++j) {
            const int r  = ((yy >> 1) + j) & 3;
            ae = f2fma(ae, GG0[ky0 + 2*j], PE[r]);
            ae = f2fma(ae, GG1[ky0 + 2*j], QE[r]);
            ao = f2fma(ao, GG0[ky0 + 2*j], PO[r]);
            ao = f2fma(ao, GG1[ky0 + 2*j], QO[r]);
        }
        out[(size_t)yy * (RESW*32)]      = ae;
        out[(size_t)yy * (RESW*32) + 32] = ao;
    }
    #undef MKROW1
}

// =====================================================================
// Recon level 1 -> 0 (padded input, polyphase-paired xo, float2 lanes,
// immediate coefficients). (round-10, measured good)
// =====================================================================
__global__ __launch_bounds__(128) void k_rec2(float* __restrict__ outp) {
    const int lane = threadIdx.x & 31;                        // float2 ch index
    const int xo   = ((blockIdx.x << 2) + (threadIdx.x >> 5)) << 1;  // even, 0..126
    const int y0   = blockIdx.y << 3;
    const int b    = blockIdx.z;

    const int vb = xo >> 1;

    const float2* __restrict__ in = reinterpret_cast<const float2*>(g_res)
        + (size_t)b * (RESPIX*32) + lane;

    float2 PE[4], PO[4];
    const int ub = ((y0 - 2) >> 1) + 1;

    #define MKROW2(REL) do {                                                 \
        const size_t rb = ((size_t)(ub + (REL))*RESW + vb)*32;               \
        float2 pe = f2z(), po = f2z();                                       \
        _Pragma("unroll")                                                    \
        for (int j = 0; j < 4; ++j) {                                        \
            const float2 v = in[rb + (size_t)j*32];                          \
            pe = f2fma(pe, GG0[1+2*j], v);                                   \
            po = f2fma(po, GG0[2*j],   v);                                   \
        }                                                                    \
        PE[(REL) & 3] = pe; PO[(REL) & 3] = po;                              \
    } while (0)

    MKROW2(0); MKROW2(1); MKROW2(2); MKROW2(3);

    float2* __restrict__ out = reinterpret_cast<float2*>(outp)
        + (((size_t)(b*128 + y0))*128 + xo)*32 + lane;

    #pragma unroll
    for (int yy = 0; yy < 8; ++yy) {
        if (yy >= 2 && (yy & 1) == 0) {
            MKROW2(yy/2 + 3);
        }
        float2 ae = f2z(), ao = f2z();
        const int ky0 = (yy & 1) ^ 1;
        #pragma unroll
        for (int j = 0; j < 4; ++j) {
            const int r = ((yy >> 1) + j) & 3;
            ae = f2fma(ae, GG0[ky0 + 2*j], PE[r]);
            ao = f2fma(ao, GG0[ky0 + 2*j], PO[r]);
        }
        out[(size_t)yy * (128*32)]      = ae;
        out[(size_t)yy * (128*32) + 32] = ao;
    }
    #undef MKROW2
}

// =====================================================================
extern "C" void kernel_launch(void* const* d_in, const int* in_sizes, int n_in,
                              void* d_out, int out_size) {
    (void)in_sizes; (void)n_in; (void)out_size;
    const float* x  = (const float*)d_in[0];
    const float* w1 = (const float*)d_in[1];
    const float* w2 = (const float*)d_in[2];
    const float* w3 = (const float*)d_in[3];
    const float* w4 = (const float*)d_in[4];
    float* out = (float*)d_out;

    k_dwt1<<<dim3(8, 8, BATCH), 128>>>(x);
    k_dwt2<<<dim3(4, 8, BATCH), 128>>>();
    k_mixw<<<dim3(8, 32, 4), 256>>>(w1, w2, w3, w4);
    k_rec1<<<dim3(8, 8, BATCH), 128>>>();
    k_rec2<<<dim3(16, 16, BATCH), 128>>>(out);
}

// round 14
// speedup vs baseline: 1.0603x; 1.0603x over previous
#include <cuda_runtime.h>
#include <cstdint>
#include <cstddef>

// ---------------- problem constants ----------------
#define BATCH 32
#define C 64
#define C4 16

// Compile-time filter constants: fold into FFMA immediates.
static __device__ constexpr float HH0[8] = {
    0.0322231f, -0.01260397f, -0.09921954f, 0.2978578f,
    0.80373875f, 0.49761867f, -0.02963553f, -0.07576571f};
static __device__ constexpr float HH1[8] = {
    0.07576571f, -0.02963553f, -0.49761867f, 0.80373875f,
   -0.2978578f, -0.09921954f, 0.01260397f, 0.0322231f};
// g = reverse(h)
static __device__ constexpr float GG0[8] = {
   -0.07576571f, -0.02963553f, 0.49761867f, 0.80373875f,
    0.2978578f, -0.09921954f, -0.01260397f, 0.0322231f};
static __device__ constexpr float GG1[8] = {
    0.0322231f, 0.01260397f, -0.09921954f, -0.2978578f,
    0.80373875f, -0.49761867f, -0.02963553f, 0.07576571f};

// ---------------- scratch (static __device__, no allocs) ----------------
#define SUBSZ  (BATCH*32*32*64)

// padded y1: per b plane 72x72 pixels, interior at (3..66, 3..66)
#define Y1W    72
#define Y1PIX  (Y1W*Y1W)

// padded mix: per (s,b) plane 36x36, interior (1..32)
#define MIXW   36
#define MIXPIX (MIXW*MIXW)
#define MIXSUBSTRIDE_F2 (32*MIXPIX*32)   // float2 stride between subbands

// padded res: per b plane 68x68, interior (1..64)
#define RESW   68
#define RESPIX (RESW*RESW)

static __device__ float g_y1 [BATCH*(size_t)Y1PIX*64];     // padded, pads stay zero
static __device__ float g_sub[4*SUBSZ];
static __device__ float g_mix[4*BATCH*(size_t)MIXPIX*64];  // padded, pads stay zero
static __device__ float g_res[BATCH*(size_t)RESPIX*64];    // padded, pads stay zero

__device__ __forceinline__ float4 f4z() { return make_float4(0.f,0.f,0.f,0.f); }
__device__ __forceinline__ float4 f4fma(float4 a, float s, float4 v) {
    a.x = fmaf(s, v.x, a.x); a.y = fmaf(s, v.y, a.y);
    a.z = fmaf(s, v.z, a.z); a.w = fmaf(s, v.w, a.w);
    return a;
}
__device__ __forceinline__ float2 f2z() { return make_float2(0.f,0.f); }
__device__ __forceinline__ float2 f2fma(float2 a, float s, float2 v) {
    a.x = fmaf(s, v.x, a.x); a.y = fmaf(s, v.y, a.y);
    return a;
}
__device__ __forceinline__ unsigned long long dup2(float a) {
    unsigned long long r;
    asm("mov.b64 %0, {%1, %1};" : "=l"(r) : "f"(a));
    return r;
}
__device__ __forceinline__ unsigned long long pk2(float x, float y) {
    unsigned long long r;
    asm("mov.b64 %0, {%1, %2};" : "=l"(r) : "f"(x), "f"(y));
    return r;
}
__device__ __forceinline__ void unpk2(unsigned long long v, float& lo, float& hi) {
    asm("mov.b64 {%0, %1}, %2;" : "=f"(lo), "=f"(hi) : "l"(v));
}

// =====================================================================
// Stage 1: level-1 LL DWT. x(B,128,128,64) -> padded g_y1. (round-12)
// block 128 = 16 lanes x 8 xo; grid (8 xtiles, 8 ychunks(8), B)
// =====================================================================
__global__ __launch_bounds__(128) void k_dwt1(const float* __restrict__ x) {
    const int lane = threadIdx.x & 15;
    const int xo   = (blockIdx.x << 3) + (threadIdx.x >> 4);  // 0..63
    const int y0   = blockIdx.y << 3;
    const int b    = blockIdx.z;
    const float4* __restrict__ xin =
        reinterpret_cast<const float4*>(x) + (size_t)b * (128*128*16) + lane;

    int   xoff[8];
    float wk[8];
    #pragma unroll
    for (int k = 0; k < 8; ++k) {
        const int xi = 2*xo - 3 + k;
        const bool v = (xi >= 0 && xi < 128);
        xoff[k] = (v ? xi : 0) * 16;
        wk[k]   = v ? HH0[k] : 0.f;
    }

    float4 H[8];

    #define DROW(REL) do {                                                   \
        const int r_ = 2*y0 + (REL);                                         \
        float4 acc_ = f4z();                                                 \
        if (r_ >= 0 && r_ < 128) {                                           \
            const size_t rb = (size_t)r_ * (128*16);                         \
            _Pragma("unroll")                                                \
            for (int k = 0; k < 8; ++k)                                      \
                acc_ = f4fma(acc_, wk[k], xin[rb + xoff[k]]);                \
        }                                                                    \
        H[((REL) + 16) & 7] = acc_;                                          \
    } while (0)

    DROW(-3); DROW(-2); DROW(-1); DROW(0); DROW(1); DROW(2);

    float4* __restrict__ yout = reinterpret_cast<float4*>(g_y1)
        + ((size_t)b*Y1PIX + (size_t)(y0 + 3)*Y1W + (xo + 3))*16 + lane;

    #pragma unroll
    for (int yy = 0; yy < 8; ++yy) {
        DROW(2*yy + 3);
        DROW(2*yy + 4);
        float4 acc = f4z();
        #pragma unroll
        for (int k = 0; k < 8; ++k)
            acc = f4fma(acc, HH0[k], H[(2*yy - 3 + k + 16) & 7]);
        yout[(size_t)yy * (Y1W*16)] = acc;
    }
    #undef DROW
}

// =====================================================================
// Stage 2: level-2 DWT (padded input, no predicates, round-12 form),
// y-chunk split 8 -> 4 (grid 512 -> 1024 blocks) for chip fill.
// block 128 = 16 lanes x 8 xo; grid (4 xtiles, 8 ychunks(4), B)
// =====================================================================
__global__ __launch_bounds__(128) void k_dwt2() {
    const int lane = threadIdx.x & 15;
    const int xo   = (blockIdx.x << 3) + (threadIdx.x >> 4);  // 0..31
    const int y0   = blockIdx.y << 2;                         // 4 per chunk
    const int b    = blockIdx.z;
    const float4* __restrict__ in =
        reinterpret_cast<const float4*>(g_y1) + (size_t)b * (Y1PIX*16) + lane;

    float4 H0[8], H1[8];

    #define D2ROW(REL) do {                                                  \
        const size_t rb = (size_t)(2*y0 + (REL) + 3) * (Y1W*16)              \
                        + (size_t)(2*xo)*16;                                 \
        float4 a0 = f4z(), a1 = f4z();                                       \
        _Pragma("unroll")                                                    \
        for (int k = 0; k < 8; ++k) {                                        \
            const float4 v = in[rb + (size_t)k*16];                          \
            a0 = f4fma(a0, HH0[k], v);                                       \
            a1 = f4fma(a1, HH1[k], v);                                       \
        }                                                                    \
        H0[((REL) + 16) & 7] = a0; H1[((REL) + 16) & 7] = a1;                \
    } while (0)

    D2ROW(-3); D2ROW(-2); D2ROW(-1); D2ROW(0); D2ROW(1); D2ROW(2);

    float4* __restrict__ sub = reinterpret_cast<float4*>(g_sub);

    #pragma unroll
    for (int yy = 0; yy < 4; ++yy) {
        D2ROW(2*yy + 3);
        D2ROW(2*yy + 4);
        float4 ll = f4z(), lh = f4z(), hl = f4z(), hh = f4z();
        #pragma unroll
        for (int k = 0; k < 8; ++k) {
            const int r = (2*yy - 3 + k + 16) & 7;
            const float4 p0 = H0[r];
            const float4 p1 = H1[r];
            ll = f4fma(ll, HH0[k], p0);
            lh = f4fma(lh, HH0[k], p1);
            hl = f4fma(hl, HH1[k], p0);
            hh = f4fma(hh, HH1[k], p1);
        }
        const size_t o = (((size_t)(b*32 + y0 + yy))*32 + xo)*16 + lane;
        sub[o + 0*(size_t)(SUBSZ/4)] = ll;
        sub[o + 1*(size_t)(SUBSZ/4)] = lh;
        sub[o + 2*(size_t)(SUBSZ/4)] = hl;
        sub[o + 3*(size_t)(SUBSZ/4)] = hh;
    }
    #undef D2ROW
}

// =====================================================================
// Fused channel mixing (round-12 form, measured good).
// =====================================================================
__global__ __launch_bounds__(256) void k_mixw(const float* __restrict__ w1,
                                              const float* __restrict__ w2,
                                              const float* __restrict__ w3,
                                              const float* __restrict__ w4) {
    const int s  = blockIdx.z;
    const int h  = blockIdx.y;
    const int w0 = blockIdx.x * 4;

    const float* __restrict__ Wg =
        (s == 0) ? w1 : (s == 1) ? w2 : (s == 2) ? w3 : w4;
    const float* __restrict__ A = g_sub + (size_t)s * SUBSZ;

    __shared__ float Ws[16*4*64];   // [i16][w4][o64]  16KB
    __shared__ float As[4*16*32];   // [w4][i16][b32]   8KB

    const int t    = threadIdx.x;
    const int wl   = t >> 5;        // 0..7
    const int wloc = wl & 3;        // local w
    const int o0   = (wl >> 2) * 32;// o half
    const int lane = t & 31;
    const int og   = lane & 7;      // o = o0 + og*4 .. +3
    const int bg   = lane >> 3;     // b = bg*8 .. +7

    unsigned long long acc[4][4];
    #pragma unroll
    for (int j = 0; j < 4; ++j)
        #pragma unroll
        for (int p = 0; p < 4; ++p) acc[j][p] = 0ull;

    const int a_b = t & 31;
    const int a_w = (t >> 5) & 3;
    const int a_i = (t >> 7) * 8;

    #pragma unroll 1
    for (int ic = 0; ic < 4; ++ic) {
        const int ib = ic * 16;
        if (ic) __syncthreads();

        #pragma unroll
        for (int r = 0; r < 4; ++r) {
            const int id = t + 256*r;
            const int o  = id & 63;
            const int i  = id >> 6;
            const float4 v = *reinterpret_cast<const float4*>(
                &Wg[((size_t)(ib + i)*64 + o)*1024 + h*32 + w0]);
            const int base = i*4*64 + o;
            Ws[base + 0*64] = v.x;
            Ws[base + 1*64] = v.y;
            Ws[base + 2*64] = v.z;
            Ws[base + 3*64] = v.w;
        }

        #pragma unroll
        for (int i4 = 0; i4 < 2; ++i4) {
            const float4 v = *reinterpret_cast<const float4*>(
                &A[((size_t)(a_b*32 + h)*32 + w0 + a_w)*64 + ib + a_i + i4*4]);
            const int base = (a_w*16 + a_i + i4*4)*32 + a_b;
            As[base + 0*32] = v.x;
            As[base + 1*32] = v.y;
            As[base + 2*32] = v.z;
            As[base + 3*32] = v.w;
        }
        __syncthreads();

        #pragma unroll
        for (int i = 0; i < 16; ++i) {
            const float4 a0 = *reinterpret_cast<const float4*>(
                &As[(wloc*16 + i)*32 + bg*8]);
            const float4 a1 = *reinterpret_cast<const float4*>(
                &As[(wloc*16 + i)*32 + bg*8 + 4]);
            const float4 wv = *reinterpret_cast<const float4*>(
                &Ws[(i*4 + wloc)*64 + o0 + og*4]);

            unsigned long long ap[4];
            ap[0] = pk2(a0.x, a0.y);
            ap[1] = pk2(a0.z, a0.w);
            ap[2] = pk2(a1.x, a1.y);
            ap[3] = pk2(a1.z, a1.w);
            unsigned long long wd[4];
            wd[0] = dup2(wv.x);
            wd[1] = dup2(wv.y);
            wd[2] = dup2(wv.z);
            wd[3] = dup2(wv.w);

            #pragma unroll
            for (int j = 0; j < 4; ++j)
                #pragma unroll
                for (int p = 0; p < 4; ++p)
                    asm("fma.rn.f32x2 %0, %1, %2, %0;"
                        : "+l"(acc[j][p]) : "l"(ap[p]), "l"(wd[j]));
        }
    }

    float af[4][8];
    #pragma unroll
    for (int j = 0; j < 4; ++j)
        #pragma unroll
        for (int p = 0; p < 4; ++p)
            unpk2(acc[j][p], af[j][2*p], af[j][2*p + 1]);

    #pragma unroll
    for (int jb = 0; jb < 8; ++jb) {
        const int b = bg*8 + jb;
        float4 v = make_float4(af[0][jb], af[1][jb], af[2][jb], af[3][jb]);
        const size_t px = ((size_t)(s*32 + b)*MIXW + (h + 1))*MIXW + (w0 + wloc + 1);
        *reinterpret_cast<float4*>(&g_mix[px*64 + o0 + og*4]) = v;
    }
}

// =====================================================================
// Recon level 2 -> 1 (padded, polyphase-paired xo, float2 lanes,
// immediate coefficients). (round-10, measured good)
// =====================================================================
__global__ __launch_bounds__(128) void k_rec1() {
    const int lane = threadIdx.x & 31;                       // float2 ch index
    const int xo   = ((blockIdx.x << 2) + (threadIdx.x >> 5)) << 1;  // even
    const int y0   = blockIdx.y << 3;
    const int b    = blockIdx.z;

    const int vb = xo >> 1;

    const float2* __restrict__ m0 = reinterpret_cast<const float2*>(g_mix)
        + (size_t)b * (MIXPIX*32) + lane;
    const float2* __restrict__ m1 = m0 + 1*(size_t)MIXSUBSTRIDE_F2;
    const float2* __restrict__ m2 = m0 + 2*(size_t)MIXSUBSTRIDE_F2;
    const float2* __restrict__ m3 = m0 + 3*(size_t)MIXSUBSTRIDE_F2;

    float2 PE[4], QE[4], PO[4], QO[4];
    const int ub = ((y0 - 2) >> 1) + 1;

    #define MKROW1(REL) do {                                                 \
        const size_t rb = ((size_t)(ub + (REL))*MIXW + vb)*32;               \
        float2 pe = f2z(), qe = f2z(), po = f2z(), qo = f2z();               \
        _Pragma("unroll")                                                    \
        for (int j = 0; j < 4; ++j) {                                        \
            const size_t ix = rb + (size_t)j*32;                             \
            const float2 aft = m0[ix], alh = m1[ix];                         \
            const float2 ahl = m2[ix], ahh = m3[ix];                         \
            pe = f2fma(pe, GG0[1+2*j], aft); pe = f2fma(pe, GG1[1+2*j], alh);\
            qe = f2fma(qe, GG0[1+2*j], ahl); qe = f2fma(qe, GG1[1+2*j], ahh);\
            po = f2fma(po, GG0[2*j],   aft); po = f2fma(po, GG1[2*j],   alh);\
            qo = f2fma(qo, GG0[2*j],   ahl); qo = f2fma(qo, GG1[2*j],   ahh);\
        }                                                                    \
        PE[(REL) & 3] = pe; QE[(REL) & 3] = qe;                              \
        PO[(REL) & 3] = po; QO[(REL) & 3] = qo;                              \
    } while (0)

    MKROW1(0); MKROW1(1); MKROW1(2); MKROW1(3);

    float2* __restrict__ out = reinterpret_cast<float2*>(g_res)
        + (((size_t)b*RESW + (y0 + 1))*RESW + (xo + 1))*32 + lane;

    #pragma unroll
    for (int yy = 0; yy < 8; ++yy) {
        if (yy >= 2 && (yy & 1) == 0) {
            MKROW1(yy/2 + 3);
        }
        float2 ae = f2z(), ao = f2z();
        const int ky0 = (yy & 1) ^ 1;
        #pragma unroll
        for (int j = 0; j < 4; ++j) {
            const int r  = ((yy >> 1) + j) & 3;
            ae = f2fma(ae, GG0[ky0 + 2*j], PE[r]);
            ae = f2fma(ae, GG1[ky0 + 2*j], QE[r]);
            ao = f2fma(ao, GG0[ky0 + 2*j], PO[r]);
            ao = f2fma(ao, GG1[ky0 + 2*j], QO[r]);
        }
        out[(size_t)yy * (RESW*32)]      = ae;
        out[(size_t)yy * (RESW*32) + 32] = ao;
    }
    #undef MKROW1
}

// =====================================================================
// Recon level 1 -> 0 (padded input, polyphase-paired xo, float2 lanes,
// immediate coefficients). (round-10, measured good)
// =====================================================================
__global__ __launch_bounds__(128) void k_rec2(float* __restrict__ outp) {
    const int lane = threadIdx.x & 31;                        // float2 ch index
    const int xo   = ((blockIdx.x << 2) + (threadIdx.x >> 5)) << 1;  // even, 0..126
    const int y0   = blockIdx.y << 3;
    const int b    = blockIdx.z;

    const int vb = xo >> 1;

    const float2* __restrict__ in = reinterpret_cast<const float2*>(g_res)
        + (size_t)b * (RESPIX*32) + lane;

    float2 PE[4], PO[4];
    const int ub = ((y0 - 2) >> 1) + 1;

    #define MKROW2(REL) do {                                                 \
        const size_t rb = ((size_t)(ub + (REL))*RESW + vb)*32;               \
        float2 pe = f2z(), po = f2z();                                       \
        _Pragma("unroll")                                                    \
        for (int j = 0; j < 4; ++j) {                                        \
            const float2 v = in[rb + (size_t)j*32];                          \
            pe = f2fma(pe, GG0[1+2*j], v);                                   \
            po = f2fma(po, GG0[2*j],   v);                                   \
        }                                                                    \
        PE[(REL) & 3] = pe; PO[(REL) & 3] = po;                              \
    } while (0)

    MKROW2(0); MKROW2(1); MKROW2(2); MKROW2(3);

    float2* __restrict__ out = reinterpret_cast<float2*>(outp)
        + (((size_t)(b*128 + y0))*128 + xo)*32 + lane;

    #pragma unroll
    for (int yy = 0; yy < 8; ++yy) {
        if (yy >= 2 && (yy & 1) == 0) {
            MKROW2(yy/2 + 3);
        }
        float2 ae = f2z(), ao = f2z();
        const int ky0 = (yy & 1) ^ 1;
        #pragma unroll
        for (int j = 0; j < 4; ++j) {
            const int r = ((yy >> 1) + j) & 3;
            ae = f2fma(ae, GG0[ky0 + 2*j], PE[r]);
            ao = f2fma(ao, GG0[ky0 + 2*j], PO[r]);
        }
        out[(size_t)yy * (128*32)]      = ae;
        out[(size_t)yy * (128*32) + 32] = ao;
    }
    #undef MKROW2
}

// =====================================================================
extern "C" void kernel_launch(void* const* d_in, const int* in_sizes, int n_in,
                              void* d_out, int out_size) {
    (void)in_sizes; (void)n_in; (void)out_size;
    const float* x  = (const float*)d_in[0];
    const float* w1 = (const float*)d_in[1];
    const float* w2 = (const float*)d_in[2];
    const float* w3 = (const float*)d_in[3];
    const float* w4 = (const float*)d_in[4];
    float* out = (float*)d_out;

    k_dwt1<<<dim3(8, 8, BATCH), 128>>>(x);
    k_dwt2<<<dim3(4, 8, BATCH), 128>>>();
    k_mixw<<<dim3(8, 32, 4), 256>>>(w1, w2, w3, w4);
    k_rec1<<<dim3(8, 8, BATCH), 128>>>();
    k_rec2<<<dim3(16, 16, BATCH), 128>>>(out);
}